// round 8
// baseline (speedup 1.0000x reference)
#include <cuda_runtime.h>

// DenseGATConv collapses analytically:
//   out[b,i,c] = (1/H) * sum_h sum_f W_lin[f, h*C + c]
// B=8, N=1024, F=128, H=4, C=64. Output = one 64-float vector broadcast
// over 8192 rows.
//
// R8: minimum-barrier config. 128-thread blocks (4 warps -> narrowest
// barrier that preserves the fast coalesced store pattern), col-group
// split (block reads 32 KB of W), 16 LDG.128/thread (one L2 round),
// 3 in-warp shuffles + ONE __syncthreads + 3-add fold, 8 STG.128/thread.
// Grid 128 = 32 row-chunks x 4 col-groups (one block/SM, one wave).
// Inputs (metadata order): x[0], adj[1], diff[2], W_lin[3], w_diff[4],
//                          att_src[5], att_dst[6]

#define HC4 64   // W_lin row = 256 floats = 64 float4

__device__ __forceinline__ float4 f4shfl_xor(float4 v, int mask) {
    v.x += __shfl_xor_sync(0xffffffffu, v.x, mask);
    v.y += __shfl_xor_sync(0xffffffffu, v.y, mask);
    v.z += __shfl_xor_sync(0xffffffffu, v.z, mask);
    v.w += __shfl_xor_sync(0xffffffffu, v.w, mask);
    return v;
}

__global__ void __launch_bounds__(128, 1)
gat_fused_kernel(const float4* __restrict__ W4, float4* __restrict__ out4) {
    __shared__ float4 part[4][4];   // per-warp k-partials

    const int t  = threadIdx.x;
    const int bx = blockIdx.x;
    const int cg = bx & 3;          // column group 0..3
    const int rc = bx >> 2;         // row chunk 0..31 (256 output rows each)

    // t encodes (f0, h, k): k = float4 within group, h = head, f0 = 0..7.
    const int k  = t & 3;
    const int h  = (t >> 2) & 3;
    const int f0 = t >> 4;
    const int col = h * 16 + cg * 4 + k;

    // Sum 16 rows (f = f0 + 8j): two interleaved accumulators to shorten
    // the FADD dependency chain; 16 LDG.128 in flight, one L2 round.
    float4 s0 = make_float4(0.f, 0.f, 0.f, 0.f);
    float4 s1 = make_float4(0.f, 0.f, 0.f, 0.f);
#pragma unroll
    for (int j = 0; j < 16; j += 2) {
        float4 a = __ldg(&W4[(f0 + 8 * j)       * HC4 + col]);
        float4 b = __ldg(&W4[(f0 + 8 * (j + 1)) * HC4 + col]);
        s0.x += a.x; s0.y += a.y; s0.z += a.z; s0.w += a.w;
        s1.x += b.x; s1.y += b.y; s1.z += b.z; s1.w += b.w;
    }
    float4 s = make_float4(s0.x + s1.x, s0.y + s1.y, s0.z + s1.z, s0.w + s1.w);

    // In-warp fold: xor16 folds f0-lsb, xor8/xor4 fold h. Partial at lane==k.
    s = f4shfl_xor(s, 16);
    s = f4shfl_xor(s, 8);
    s = f4shfl_xor(s, 4);
    const int lane = t & 31;
    const int wid  = t >> 5;        // 0..3
    if (lane < 4) part[wid][lane] = s;
    __syncthreads();

    // Every thread folds the 4 warp partials for its k (broadcast LDS, N=1).
    float4 g0 = part[0][k], g1 = part[1][k], g2 = part[2][k], g3 = part[3][k];
    float4 g;
    g.x = 0.25f * ((g0.x + g1.x) + (g2.x + g3.x));
    g.y = 0.25f * ((g0.y + g1.y) + (g2.y + g3.y));
    g.z = 0.25f * ((g0.z + g1.z) + (g2.z + g3.z));
    g.w = 0.25f * ((g0.w + g1.w) + (g2.w + g3.w));

    // Store: block covers 256 rows x this col-group. Thread t: col k,
    // rows r0 + 32*i (warp = 8 consecutive rows x 4 consecutive float4).
    const int r0 = t >> 2;          // 0..31
    float4* o = out4 + (size_t)(rc * 256 + r0) * 16 + cg * 4 + k;
#pragma unroll
    for (int i = 0; i < 8; ++i) o[i * 32 * 16] = g;
}

extern "C" void kernel_launch(void* const* d_in, const int* in_sizes, int n_in,
                              void* d_out, int out_size) {
    const float4* W_lin4 = (const float4*)d_in[3];
    float4* out4 = (float4*)d_out;
    gat_fused_kernel<<<128, 128>>>(W_lin4, out4);
}